// round 10
// baseline (speedup 1.0000x reference)
#include <cuda_runtime.h>

// FractionalSTFT_42253888258226 — FINAL (converged; locked)
//
// === Why this kernel is a copy ===
// The reference builds an analysis matrix W over the fractional frequency
// grid k2 = {j/16 : j = 0..16383}, which is UNIFORM over one full period:
//   (W^H W)[n,m] = (1/N) * sum_{j=0}^{16383} exp(-i*2*pi*j*(n-m)/16384)
//               = 16 * delta_{nm}        (geometric sum, exact)
// so W is a tight frame: pinv(W) = W^H/16, pinv(W) @ W = I. The conjugate-
// symmetric extension (Xe_re/Xe_im concat) matches k2's ordering exactly for
// real frames, so synthesis returns y == frames. Overlap-add of window*xp
// divided by win_norm reconstructs xp sample-exactly (the win_norm->0 edge
// lies inside the pad=512 crop), and the crop removes the reflect padding.
// Net: out == x. Measured rel_err = 1.56e-7 = the reference's own fp32
// pinv/accumulation noise. ~2e11 FLOPs eliminated analytically.
//
// === Floor analysis (R1-R9) ===
// Nine measurements across four mechanisms (512x256 float4 kernel, 128x256
// MLP=4 kernel, cudaMemcpyAsync D2D node, exact-fit unpredicated kernel):
// 6.62, 6.78, 6.91, 6.30, 6.53, 6.46, 6.21, 6.72, 6.88 us — mechanism-
// independent; identical binaries span 6.21-6.88. Sampling noise
// (sigma ~0.2us) on a ~6.5us graph-replay floor. The 2 MiB L2-resident move
// is <1us warm; the residual is fixed overhead outside kernel control.
// No untested mechanism remains with a predicted delta above the noise
// floor; further edits would be dice-rolling, not optimization.

__global__ void fstft_copy_exact(const float4* __restrict__ src,
                                 float4* __restrict__ dst) {
    int i = blockIdx.x * blockDim.x + threadIdx.x;
    dst[i] = src[i];
}

__global__ void fstft_copy_guarded(const float4* __restrict__ src,
                                   float4* __restrict__ dst,
                                   int n_vec4) {
    int i = blockIdx.x * blockDim.x + threadIdx.x;
    if (i < n_vec4) dst[i] = src[i];
}

__global__ void fstft_copy_tail(const float* __restrict__ src,
                                float* __restrict__ dst,
                                int start, int n) {
    int i = start + blockIdx.x * blockDim.x + threadIdx.x;
    if (i < n) dst[i] = src[i];
}

extern "C" void kernel_launch(void* const* d_in, const int* in_sizes, int n_in,
                              void* d_out, int out_size) {
    const float* x = (const float*)d_in[0];   // (2, 2, 131072) fp32
    float* out = (float*)d_out;

    int n = out_size;                 // 524288
    if (n > in_sizes[0]) n = in_sizes[0];

    int n_vec4 = n >> 2;              // 131072 float4 (16B-aligned: cudaMalloc'd)
    const int block = 256;

    if ((n & 3) == 0 && (n_vec4 % block) == 0) {
        // Exact fit: 512 blocks x 256 threads, no predicate in the kernel.
        fstft_copy_exact<<<n_vec4 / block, block>>>((const float4*)x,
                                                    (float4*)out);
    } else {
        int grid = (n_vec4 + block - 1) / block;
        if (grid > 0) {
            fstft_copy_guarded<<<grid, block>>>((const float4*)x,
                                                (float4*)out, n_vec4);
        }
        int done = n_vec4 << 2;
        if (n - done > 0) {
            fstft_copy_tail<<<1, 128>>>(x, out, done, n);
        }
    }
}

// round 11
// speedup vs baseline: 1.4828x; 1.4828x over previous
#include <cuda_runtime.h>

// FractionalSTFT_42253888258226 — FINAL (converged; locked)
//
// === Why this kernel is a copy ===
// The reference builds an analysis matrix W over the fractional frequency
// grid k2 = {j/16 : j = 0..16383}, which is UNIFORM over one full period:
//   (W^H W)[n,m] = (1/N) * sum_{j=0}^{16383} exp(-i*2*pi*j*(n-m)/16384)
//               = 16 * delta_{nm}        (geometric sum, exact)
// so W is a tight frame: pinv(W) = W^H/16, pinv(W) @ W = I. The conjugate-
// symmetric extension (Xe_re/Xe_im concat) matches k2's ordering exactly for
// real frames, so synthesis returns y == frames. Overlap-add of window*xp
// divided by win_norm reconstructs xp sample-exactly (the win_norm->0 edge
// lies inside the pad=512 crop), and the crop removes the reflect padding.
// Net: out == x. Measured rel_err = 1.56e-7 = the reference's own fp32
// pinv/accumulation noise. ~2e11 FLOPs eliminated analytically.
//
// === Floor analysis (R1-R9) ===
// Nine measurements across four mechanisms (512x256 float4 kernel, 128x256
// MLP=4 kernel, cudaMemcpyAsync D2D node, exact-fit unpredicated kernel):
// 6.62, 6.78, 6.91, 6.30, 6.53, 6.46, 6.21, 6.72, 6.88 us — mechanism-
// independent; identical binaries span 6.21-6.88. Sampling noise
// (sigma ~0.2us) on a ~6.5us graph-replay floor. The 2 MiB L2-resident move
// is <1us warm; the residual is fixed overhead outside kernel control.
// No untested mechanism remains with a predicted delta above the noise
// floor; further edits would be dice-rolling, not optimization.

__global__ void fstft_copy_exact(const float4* __restrict__ src,
                                 float4* __restrict__ dst) {
    int i = blockIdx.x * blockDim.x + threadIdx.x;
    dst[i] = src[i];
}

__global__ void fstft_copy_guarded(const float4* __restrict__ src,
                                   float4* __restrict__ dst,
                                   int n_vec4) {
    int i = blockIdx.x * blockDim.x + threadIdx.x;
    if (i < n_vec4) dst[i] = src[i];
}

__global__ void fstft_copy_tail(const float* __restrict__ src,
                                float* __restrict__ dst,
                                int start, int n) {
    int i = start + blockIdx.x * blockDim.x + threadIdx.x;
    if (i < n) dst[i] = src[i];
}

extern "C" void kernel_launch(void* const* d_in, const int* in_sizes, int n_in,
                              void* d_out, int out_size) {
    const float* x = (const float*)d_in[0];   // (2, 2, 131072) fp32
    float* out = (float*)d_out;

    int n = out_size;                 // 524288
    if (n > in_sizes[0]) n = in_sizes[0];

    int n_vec4 = n >> 2;              // 131072 float4 (16B-aligned: cudaMalloc'd)
    const int block = 256;

    if ((n & 3) == 0 && (n_vec4 % block) == 0) {
        // Exact fit: 512 blocks x 256 threads, no predicate in the kernel.
        fstft_copy_exact<<<n_vec4 / block, block>>>((const float4*)x,
                                                    (float4*)out);
    } else {
        int grid = (n_vec4 + block - 1) / block;
        if (grid > 0) {
            fstft_copy_guarded<<<grid, block>>>((const float4*)x,
                                                (float4*)out, n_vec4);
        }
        int done = n_vec4 << 2;
        if (n - done > 0) {
            fstft_copy_tail<<<1, 128>>>(x, out, done, n);
        }
    }
}